// round 6
// baseline (speedup 1.0000x reference)
#include <cuda_runtime.h>
#include <cstdint>
#include <cstddef>

#define DEVFN __device__ __forceinline__
typedef unsigned long long u64t;

// ---------------- static device scratch (no cudaMalloc allowed) -------------
__device__ float g_xproj[16 * 1024 * 1024]; // [bt][1024] gate pre-activations (reused for both layers)
__device__ float g_h0[16 * 1024 * 256];     // layer-0 hidden states
__device__ float g_h1[16 * 1024 * 256];     // layer-1 hidden states

// ---------------- helpers ----------------------------------------------------
DEVFN uint32_t smem_u32(const void* p) {
    uint32_t a;
    asm("{ .reg .u64 t; cvta.to.shared.u64 t, %1; cvt.u32.u64 %0, t; }" : "=r"(a) : "l"(p));
    return a;
}
DEVFN float frcp_(float x) { float r; asm("rcp.approx.f32 %0, %1;" : "=f"(r) : "f"(x)); return r; }
DEVFN float fexp2_(float x) { float r; asm("ex2.approx.f32 %0, %1;" : "=f"(r) : "f"(x)); return r; }
DEVFN float sigm_(float x) { return frcp_(1.0f + fexp2_(-1.4426950408889634f * x)); }
DEVFN float tanh_(float x) { return 1.0f - 2.0f * frcp_(1.0f + fexp2_(2.8853900817779268f * x)); }
DEVFN void cluster_sync_() {
    asm volatile("barrier.cluster.arrive.aligned;\n\tbarrier.cluster.wait.aligned;\n" ::: "memory");
}
DEVFN u64t ffma2_(u64t a, u64t b, u64t c) {
    u64t d;
    asm("fma.rn.f32x2 %0, %1, %2, %3;" : "=l"(d) : "l"(a), "l"(b), "l"(c));
    return d;
}
DEVFN u64t add2_(u64t a, u64t b) {
    u64t d;
    asm("add.rn.f32x2 %0, %1, %2;" : "=l"(d) : "l"(a), "l"(b));
    return d;
}
DEVFN float pairsum_(u64t s) {
    return __uint_as_float((uint32_t)s) + __uint_as_float((uint32_t)(s >> 32));
}
DEVFN uint32_t mapa_(uint32_t addr, uint32_t peer) {
    uint32_t r;
    asm("mapa.shared::cluster.u32 %0, %1, %2;" : "=r"(r) : "r"(addr), "r"(peer));
    return r;
}
DEVFN void mbar_init_(uint32_t a, uint32_t cnt) {
    asm volatile("mbarrier.init.shared.b64 [%0], %1;" :: "r"(a), "r"(cnt) : "memory");
}
DEVFN void mbar_expect_(uint32_t a, uint32_t bytes) {
    asm volatile("mbarrier.arrive.expect_tx.shared.b64 _, [%0], %1;" :: "r"(a), "r"(bytes) : "memory");
}
DEVFN void mbar_wait_(uint32_t a, uint32_t par) {
    asm volatile(
        "{\n\t.reg .pred P;\n\t"
        "W%=:\n\t"
        "mbarrier.try_wait.parity.acquire.cluster.shared::cta.b64 P, [%0], %1, 0x989680;\n\t"
        "@!P bra W%=;\n\t}"
        :: "r"(a), "r"(par) : "memory");
}
// remote SMEM 8-byte store with tx-byte completion on the remote CTA's mbarrier
DEVFN void st_async_u64_(uint32_t raddr, u64t v, uint32_t rmbar) {
    asm volatile(
        "st.async.shared::cluster.mbarrier::complete_tx::bytes.b64 [%0], %1, [%2];"
        :: "r"(raddr), "l"(v), "r"(rmbar) : "memory");
}

// ============================================================================
// GEMM: C[m][n] = sum_k A[m][k]*B[n][k] + bias1[n] + bias2[n]
// A: (16384, K), B: (1024, K), C: g_xproj (16384, 1024). K in {32, 256}.
// ============================================================================
__global__ void __launch_bounds__(256, 4)
gemm_xproj(const float* __restrict__ A, const float* __restrict__ B,
           const float* __restrict__ bias1, const float* __restrict__ bias2,
           float* __restrict__ C, int K)
{
    __shared__ __align__(16) float As[32][68];
    __shared__ __align__(16) float Bs[32][68];

    const int tid = threadIdx.x;
    const int tx = tid & 15, ty = tid >> 4;
    const int m0 = blockIdx.y * 64, n0 = blockIdx.x * 64;
    const int lr = tid >> 2;
    const int lcb = (tid & 3) * 4;

    float acc[4][4] = {};

    for (int kk = 0; kk < K; kk += 32) {
#pragma unroll
        for (int it = 0; it < 2; it++) {
            int k0 = lcb + it * 16;
            float4 a = *(const float4*)(A + (size_t)(m0 + lr) * K + kk + k0);
            As[k0 + 0][lr] = a.x; As[k0 + 1][lr] = a.y;
            As[k0 + 2][lr] = a.z; As[k0 + 3][lr] = a.w;
            float4 bb = *(const float4*)(B + (size_t)(n0 + lr) * K + kk + k0);
            Bs[k0 + 0][lr] = bb.x; Bs[k0 + 1][lr] = bb.y;
            Bs[k0 + 2][lr] = bb.z; Bs[k0 + 3][lr] = bb.w;
        }
        __syncthreads();
#pragma unroll
        for (int k = 0; k < 32; k++) {
            float4 av = *(const float4*)&As[k][ty * 4];
            float4 bv = *(const float4*)&Bs[k][tx * 4];
            float am[4] = {av.x, av.y, av.z, av.w};
            float bn[4] = {bv.x, bv.y, bv.z, bv.w};
#pragma unroll
            for (int i = 0; i < 4; i++)
#pragma unroll
                for (int jn = 0; jn < 4; jn++)
                    acc[i][jn] = fmaf(am[i], bn[jn], acc[i][jn]);
        }
        __syncthreads();
    }
    float4 b1 = *(const float4*)(bias1 + n0 + tx * 4);
    float4 b2 = *(const float4*)(bias2 + n0 + tx * 4);
    float bad[4] = {b1.x + b2.x, b1.y + b2.y, b1.z + b2.z, b1.w + b2.w};
#pragma unroll
    for (int i = 0; i < 4; i++) {
        float4 o;
        o.x = acc[i][0] + bad[0]; o.y = acc[i][1] + bad[1];
        o.z = acc[i][2] + bad[2]; o.w = acc[i][3] + bad[3];
        *(float4*)(C + (size_t)(m0 + ty * 4 + i) * 1024 + n0 + tx * 4) = o;
    }
}

// ============================================================================
// LSTM recurrence. 8-CTA cluster per batch element; grid = 128 CTAs x 512 thr.
// CTA rank r owns h indices [32r, 32r+32).
// Thread tid -> (q = tid&3: column quarter of 64, g = (tid>>2)&3: gate,
//                j = tid>>4: h index). Warp w holds j = 2w, 2w+1 entirely.
// Per step per warp: 16 LDS.128 (bank-staggered by q, conflict-free) +
// 32 ffma2 + 2 butterfly shfl (quarter reduce) + 3 idx shfl (gate gather) ->
// lanes 0,16 apply activations; lane 0 packs both h values and sends one
// st.async.b64 to each of the 8 CTAs. NO __syncthreads in the loop: each
// warp's st.async is data-dependent on all its hbuf reads, so phase t+1
// overwrites cannot precede any warp's phase-t reads.
// Dual-parity mbarriers (slack-2) as in R3.
// ============================================================================
__global__ void __cluster_dims__(8, 1, 1) __launch_bounds__(512, 1)
lstm_kernel(const float* __restrict__ Whh, const float* __restrict__ xproj,
            float* __restrict__ hout)
{
    __shared__ __align__(16) float hbuf[2][256];
    __shared__ __align__(8)  unsigned long long mbar[2];

    const int tid  = threadIdx.x;
    const int q    = tid & 3;
    const int g    = (tid >> 2) & 3;
    const int j    = tid >> 4;
    const int lane = tid & 31;
    const int w    = tid >> 5;
    uint32_t rank;
    asm("mov.u32 %0, %%cluster_ctarank;" : "=r"(rank));
    const int b = blockIdx.x >> 3;
    const int base = (int)rank * 32;

    // W registers: chunk i holds columns 64q + 4*((i+q)&15) (rotation matches
    // the staggered LDS pattern below)
    ulonglong2 W[16];
    {
        const ulonglong2* wrow =
            (const ulonglong2*)(Whh + (size_t)(g * 256 + base + j) * 256 + q * 64);
#pragma unroll
        for (int i = 0; i < 16; i++) W[i] = wrow[(i + q) & 15];
    }

    if (tid < 256) hbuf[0][tid] = 0.0f;
    const uint32_t mb0 = smem_u32(&mbar[0]);     // mb1 = mb0 + 8
    const uint32_t hb0 = smem_u32(&hbuf[0][0]);
    if (tid == 0) { mbar_init_(mb0, 1); mbar_init_(mb0 + 8, 1); }
    __syncthreads();
    cluster_sync_();   // peers' mbarriers + zeroed hbuf visible before any st.async

    const bool prod = (lane & 15) == 0;          // lanes 0 and 16
    const int jm = 2 * w + (lane >> 4);          // producer's h index within CTA
    const float* xr = xproj + (size_t)b * 1024 * 1024 + base + jm;

    uint32_t rdst[8], rmb[8];
    if (lane == 0) {
        uint32_t dslot = hb0 + (uint32_t)(base + 2 * w) * 4;
#pragma unroll
        for (int r = 0; r < 8; r++) {
            rdst[r] = mapa_(dslot, (uint32_t)r);
            rmb[r]  = mapa_(mb0, (uint32_t)r);   // +8 selects the other barrier
        }
    }

    float c = 0.0f;
    float xn0 = 0.f, xn1 = 0.f, xn2 = 0.f, xn3 = 0.f;
    if (prod) { xn0 = xr[0]; xn1 = xr[256]; xn2 = xr[512]; xn3 = xr[768]; }

#pragma unroll 1
    for (int t = 0; t < 1024; t++) {
        float xc0 = xn0, xc1 = xn1, xc2 = xn2, xc3 = xn3;
        if (prod && t < 1023) {                  // prefetch next step (fully hidden)
            const float* x2 = xr + (size_t)(t + 1) * 1024;
            xn0 = x2[0]; xn1 = x2[256]; xn2 = x2[512]; xn3 = x2[768];
        }
        if (t > 0) mbar_wait_(mb0 + ((t & 1) ? 0u : 8u), (uint32_t)(((t - 1) >> 1) & 1));
        if (tid == 0 && t < 1023) mbar_expect_(mb0 + ((t & 1) ? 8u : 0u), 1024);

        const ulonglong2* hb = (const ulonglong2*)(hbuf[t & 1]) + q * 16;
        u64t a0 = 0ULL, a1 = 0ULL, a2 = 0ULL, a3 = 0ULL;
#pragma unroll
        for (int i = 0; i < 16; i += 4) {
            ulonglong2 H0 = hb[(i + 0 + q) & 15];
            ulonglong2 H1 = hb[(i + 1 + q) & 15];
            ulonglong2 H2 = hb[(i + 2 + q) & 15];
            ulonglong2 H3 = hb[(i + 3 + q) & 15];
            a0 = ffma2_(W[i + 0].x, H0.x, a0); a0 = ffma2_(W[i + 0].y, H0.y, a0);
            a1 = ffma2_(W[i + 1].x, H1.x, a1); a1 = ffma2_(W[i + 1].y, H1.y, a1);
            a2 = ffma2_(W[i + 2].x, H2.x, a2); a2 = ffma2_(W[i + 2].y, H2.y, a2);
            a3 = ffma2_(W[i + 3].x, H3.x, a3); a3 = ffma2_(W[i + 3].y, H3.y, a3);
        }
        a0 = add2_(a0, a1); a2 = add2_(a2, a3); a0 = add2_(a0, a2);
        float r = pairsum_(a0);
        // reduce over the 4 column-quarters
        r += __shfl_xor_sync(0xffffffffu, r, 1);
        r += __shfl_xor_sync(0xffffffffu, r, 2);
        // gather the 4 gate sums into lanes 0 / 16
        const int gb = lane & 16;
        float v1 = __shfl_sync(0xffffffffu, r, gb + 4);
        float v2 = __shfl_sync(0xffffffffu, r, gb + 8);
        float v3 = __shfl_sync(0xffffffffu, r, gb + 12);
        float hval = 0.0f;
        if (prod) {
            float iv = sigm_(r  + xc0);
            float fv = sigm_(v1 + xc1);
            float gg = tanh_(v2 + xc2);
            float ov = sigm_(v3 + xc3);
            c = fmaf(fv, c, iv * gg);
            hval = ov * tanh_(c);
        }
        float hhi = __shfl_sync(0xffffffffu, hval, 16);
        if (lane == 0) {
            u64t pk = (u64t)__float_as_uint(hval) | ((u64t)__float_as_uint(hhi) << 32);
            *(u64t*)(hout + (size_t)(b * 1024 + t) * 256 + base + 2 * w) = pk;
            if (t < 1023) {
                uint32_t boff = (uint32_t)(((t + 1) & 1) * 1024);
                uint32_t msel = (t & 1) ? 8u : 0u;
#pragma unroll
                for (int rr = 0; rr < 8; rr++)
                    st_async_u64_(rdst[rr] + boff, pk, rmb[rr] + msel);
            }
        }
    }
    cluster_sync_();   // don't exit while stores targeting peers may be in flight
}

// ============================================================================
// Attention (last timestep only, algebraically reduced) + output heads.
// ============================================================================
#define ATTN_SMEM_FLOATS 17416
#define ATTN_SMEM_BYTES (ATTN_SMEM_FLOATS * 4)

__global__ void __launch_bounds__(256, 1)
attn_kernel(const float* __restrict__ h1all,
            const float* __restrict__ Wq, const float* __restrict__ bq,
            const float* __restrict__ Wk, const float* __restrict__ bk,
            const float* __restrict__ Wv, const float* __restrict__ bv,
            const float* __restrict__ Wo, const float* __restrict__ bo,
            const float* __restrict__ Wm, const float* __restrict__ bm,
            const float* __restrict__ Wvar, const float* __restrict__ bvar,
            float* __restrict__ out)
{
    extern __shared__ float sm[];
    float* tile   = sm;           // 16 x 256
    float* scores = sm + 4096;    // 8 x 1024
    float* u      = sm + 12288;   // 8 x 256
    float* hb     = sm + 14336;   // 8 x 256
    float* qv     = sm + 16384;   // 256
    float* h2last = sm + 16640;   // 256
    float* attnv  = sm + 16896;   // 256
    float* ctx    = sm + 17152;   // 256
    float* qb     = sm + 17408;   // 8

    const int b = blockIdx.x;
    const int tid = threadIdx.x;
    const int w = tid >> 5, lane = tid & 31;
    const float* hbase = h1all + (size_t)b * 1024 * 256;

    h2last[tid] = hbase[1023 * 256 + tid];
    __syncthreads();

    {
        float acc = bq[tid];
        const float* wr = Wq + (size_t)tid * 256;
#pragma unroll 8
        for (int d = 0; d < 256; d++) acc = fmaf(wr[d], h2last[d], acc);
        qv[tid] = acc;
    }
    __syncthreads();

#pragma unroll 1
    for (int i = 0; i < 8; i++) {
        int flat = tid + (i << 8);
        int hh = flat >> 8, d = flat & 255;
        float acc = 0.0f;
        const float* basep = Wk + (size_t)hh * 32 * 256 + d;
#pragma unroll
        for (int e = 0; e < 32; e++) acc = fmaf(basep[(size_t)e * 256], qv[(hh << 5) + e], acc);
        u[hh * 256 + d] = acc;
    }
    if (tid < 8) {
        float a = 0.0f;
        for (int e = 0; e < 32; e++) a = fmaf(qv[tid * 32 + e], bk[tid * 32 + e], a);
        qb[tid] = a;
    }
    __syncthreads();

    const float scale = 0.17677669529663687f;   // 1/sqrt(32)
    const float L2D   = -0.07400058144377693f;  // log2(0.95)
    const float LOG2E = 1.4426950408889634f;
    float mmax = -1e30f;

#pragma unroll 1
    for (int tt = 0; tt < 64; tt++) {
        {
            int tl = tid >> 4, d0 = (tid & 15) * 16;
            const float4* src = (const float4*)(hbase + (size_t)(tt * 16 + tl) * 256 + d0);
            float4* dst = (float4*)(tile + tl * 256 + d0);
            dst[0] = src[0]; dst[1] = src[1]; dst[2] = src[2]; dst[3] = src[3];
        }
        __syncthreads();
#pragma unroll 1
        for (int tl = 0; tl < 16; tl++) {
            int t = tt * 16 + tl;
            float part = 0.0f;
            const float* tr = tile + tl * 256 + lane * 8;
            const float* ur = u + w * 256 + lane * 8;
#pragma unroll
            for (int i = 0; i < 8; i++) part = fmaf(ur[i], tr[i], part);
#pragma unroll
            for (int m = 16; m > 0; m >>= 1) part += __shfl_xor_sync(0xffffffffu, part, m);
            float s = (part + qb[w]) * scale * fexp2_((float)(1023 - t) * L2D);
            if (lane == 0) scores[w * 1024 + t] = s;
            mmax = fmaxf(mmax, s);
        }
        __syncthreads();
    }

    float Z = 0.0f;
    for (int t = lane; t < 1024; t += 32) Z += fexp2_(LOG2E * (scores[w * 1024 + t] - mmax));
#pragma unroll
    for (int m = 16; m > 0; m >>= 1) Z += __shfl_xor_sync(0xffffffffu, Z, m);
    float invZ = 1.0f / Z;

    float hbar[8] = {0, 0, 0, 0, 0, 0, 0, 0};
#pragma unroll 1
    for (int tt = 0; tt < 64; tt++) {
        {
            int tl = tid >> 4, d0 = (tid & 15) * 16;
            const float4* src = (const float4*)(hbase + (size_t)(tt * 16 + tl) * 256 + d0);
            float4* dst = (float4*)(tile + tl * 256 + d0);
            dst[0] = src[0]; dst[1] = src[1]; dst[2] = src[2]; dst[3] = src[3];
        }
        __syncthreads();
#pragma unroll 1
        for (int tl = 0; tl < 16; tl++) {
            int t = tt * 16 + tl;
            float pr = fexp2_(LOG2E * (scores[w * 1024 + t] - mmax)) * invZ;
            const float* tr = tile + tl * 256 + lane * 8;
#pragma unroll
            for (int i = 0; i < 8; i++) hbar[i] = fmaf(pr, tr[i], hbar[i]);
        }
        __syncthreads();
    }
#pragma unroll
    for (int i = 0; i < 8; i++) hb[w * 256 + lane * 8 + i] = hbar[i];
    __syncthreads();

    {
        int hh = tid >> 5;
        float acc = bv[tid];
        const float* wr = Wv + (size_t)tid * 256;
        const float* hr = hb + hh * 256;
#pragma unroll 8
        for (int d = 0; d < 256; d++) acc = fmaf(wr[d], hr[d], acc);
        attnv[tid] = acc;
    }
    __syncthreads();
    {
        float acc = bo[tid];
        const float* wr = Wo + (size_t)tid * 256;
#pragma unroll 8
        for (int d = 0; d < 256; d++) acc = fmaf(wr[d], attnv[d], acc);
        ctx[tid] = acc;
    }
    __syncthreads();
    if (tid < 5) {
        float acc = bm[tid];
        const float* wr = Wm + (size_t)tid * 256;
#pragma unroll 8
        for (int d = 0; d < 256; d++) acc = fmaf(wr[d], ctx[d], acc);
        out[b * 5 + tid] = acc;
    } else if (tid >= 32 && tid < 37) {
        int jj = tid - 32;
        float acc = bvar[jj];
        const float* wr = Wvar + (size_t)jj * 256;
#pragma unroll 8
        for (int d = 0; d < 256; d++) acc = fmaf(wr[d], ctx[d], acc);
        out[80 + b * 5 + jj] = acc;
    }
}

// ============================================================================
extern "C" void kernel_launch(void* const* d_in, const int* in_sizes, int n_in,
                              void* d_out, int out_size)
{
    (void)in_sizes; (void)n_in; (void)out_size;
    const float* x    = (const float*)d_in[0];
    const float* Wih0 = (const float*)d_in[1];
    const float* Whh0 = (const float*)d_in[2];
    const float* bih0 = (const float*)d_in[3];
    const float* bhh0 = (const float*)d_in[4];
    const float* Wih1 = (const float*)d_in[5];
    const float* Whh1 = (const float*)d_in[6];
    const float* bih1 = (const float*)d_in[7];
    const float* bhh1 = (const float*)d_in[8];
    const float* Wq   = (const float*)d_in[9];
    const float* bq   = (const float*)d_in[10];
    const float* Wk   = (const float*)d_in[11];
    const float* bk   = (const float*)d_in[12];
    const float* Wv   = (const float*)d_in[13];
    const float* bv   = (const float*)d_in[14];
    const float* Wo   = (const float*)d_in[15];
    const float* bo   = (const float*)d_in[16];
    const float* Wm   = (const float*)d_in[17];
    const float* bm   = (const float*)d_in[18];
    const float* Wvar = (const float*)d_in[19];
    const float* bvar = (const float*)d_in[20];
    float* out = (float*)d_out;

    float *xp, *h0p, *h1p;
    cudaGetSymbolAddress((void**)&xp,  g_xproj);
    cudaGetSymbolAddress((void**)&h0p, g_h0);
    cudaGetSymbolAddress((void**)&h1p, g_h1);
    cudaFuncSetAttribute(attn_kernel, cudaFuncAttributeMaxDynamicSharedMemorySize, ATTN_SMEM_BYTES);

    gemm_xproj<<<dim3(16, 256), 256>>>(x,   Wih0, bih0, bhh0, xp, 32);
    lstm_kernel<<<128, 512>>>(Whh0, xp, h0p);
    gemm_xproj<<<dim3(16, 256), 256>>>(h0p, Wih1, bih1, bhh1, xp, 256);
    lstm_kernel<<<128, 512>>>(Whh1, xp, h1p);
    attn_kernel<<<16, 256, ATTN_SMEM_BYTES>>>(h1p, Wq, bq, Wk, bk, Wv, bv, Wo, bo,
                                              Wm, bm, Wvar, bvar, out);
}

// round 7
// speedup vs baseline: 1.2480x; 1.2480x over previous
#include <cuda_runtime.h>
#include <cstdint>
#include <cstddef>

#define DEVFN __device__ __forceinline__
typedef unsigned long long u64t;

// ---------------- static device scratch (no cudaMalloc allowed) -------------
__device__ float g_xproj[16 * 1024 * 1024]; // [bt][1024] gate pre-activations (reused for both layers)
__device__ float g_h0[16 * 1024 * 256];     // layer-0 hidden states
__device__ float g_h1[16 * 1024 * 256];     // layer-1 hidden states

// ---------------- helpers ----------------------------------------------------
DEVFN uint32_t smem_u32(const void* p) {
    uint32_t a;
    asm("{ .reg .u64 t; cvta.to.shared.u64 t, %1; cvt.u32.u64 %0, t; }" : "=r"(a) : "l"(p));
    return a;
}
DEVFN float frcp_(float x) { float r; asm("rcp.approx.f32 %0, %1;" : "=f"(r) : "f"(x)); return r; }
DEVFN float fexp2_(float x) { float r; asm("ex2.approx.f32 %0, %1;" : "=f"(r) : "f"(x)); return r; }
DEVFN float sigm_(float x) { return frcp_(1.0f + fexp2_(-1.4426950408889634f * x)); }
DEVFN float tanh_(float x) { return 1.0f - 2.0f * frcp_(1.0f + fexp2_(2.8853900817779268f * x)); }
DEVFN void cluster_sync_() {
    asm volatile("barrier.cluster.arrive.aligned;\n\tbarrier.cluster.wait.aligned;\n" ::: "memory");
}
DEVFN u64t ffma2_(u64t a, u64t b, u64t c) {
    u64t d;
    asm("fma.rn.f32x2 %0, %1, %2, %3;" : "=l"(d) : "l"(a), "l"(b), "l"(c));
    return d;
}
DEVFN float pairsum_(u64t s) {
    return __uint_as_float((uint32_t)s) + __uint_as_float((uint32_t)(s >> 32));
}
DEVFN uint32_t mapa_(uint32_t addr, uint32_t peer) {
    uint32_t r;
    asm("mapa.shared::cluster.u32 %0, %1, %2;" : "=r"(r) : "r"(addr), "r"(peer));
    return r;
}
DEVFN void mbar_init_(uint32_t a, uint32_t cnt) {
    asm volatile("mbarrier.init.shared.b64 [%0], %1;" :: "r"(a), "r"(cnt) : "memory");
}
DEVFN void mbar_expect_(uint32_t a, uint32_t bytes) {
    asm volatile("mbarrier.arrive.expect_tx.shared.b64 _, [%0], %1;" :: "r"(a), "r"(bytes) : "memory");
}
DEVFN void mbar_wait_(uint32_t a, uint32_t par) {
    asm volatile(
        "{\n\t.reg .pred P;\n\t"
        "W%=:\n\t"
        "mbarrier.try_wait.parity.acquire.cluster.shared::cta.b64 P, [%0], %1, 0x989680;\n\t"
        "@!P bra W%=;\n\t}"
        :: "r"(a), "r"(par) : "memory");
}
// remote SMEM 8-byte store with tx-byte completion on the remote CTA's mbarrier
DEVFN void st_async_u64_(uint32_t raddr, u64t v, uint32_t rmbar) {
    asm volatile(
        "st.async.shared::cluster.mbarrier::complete_tx::bytes.b64 [%0], %1, [%2];"
        :: "r"(raddr), "l"(v), "r"(rmbar) : "memory");
}

// ============================================================================
// GEMM: C[m][n] = sum_k A[m][k]*B[n][k] + bias1[n] + bias2[n]
// A: (16384, K), B: (1024, K), C: g_xproj (16384, 1024). K in {32, 256}.
// ============================================================================
__global__ void __launch_bounds__(256, 4)
gemm_xproj(const float* __restrict__ A, const float* __restrict__ B,
           const float* __restrict__ bias1, const float* __restrict__ bias2,
           float* __restrict__ C, int K)
{
    __shared__ __align__(16) float As[32][68];
    __shared__ __align__(16) float Bs[32][68];

    const int tid = threadIdx.x;
    const int tx = tid & 15, ty = tid >> 4;
    const int m0 = blockIdx.y * 64, n0 = blockIdx.x * 64;
    const int lr = tid >> 2;
    const int lcb = (tid & 3) * 4;

    float acc[4][4] = {};

    for (int kk = 0; kk < K; kk += 32) {
#pragma unroll
        for (int it = 0; it < 2; it++) {
            int k0 = lcb + it * 16;
            float4 a = *(const float4*)(A + (size_t)(m0 + lr) * K + kk + k0);
            As[k0 + 0][lr] = a.x; As[k0 + 1][lr] = a.y;
            As[k0 + 2][lr] = a.z; As[k0 + 3][lr] = a.w;
            float4 bb = *(const float4*)(B + (size_t)(n0 + lr) * K + kk + k0);
            Bs[k0 + 0][lr] = bb.x; Bs[k0 + 1][lr] = bb.y;
            Bs[k0 + 2][lr] = bb.z; Bs[k0 + 3][lr] = bb.w;
        }
        __syncthreads();
#pragma unroll
        for (int k = 0; k < 32; k++) {
            float4 av = *(const float4*)&As[k][ty * 4];
            float4 bv = *(const float4*)&Bs[k][tx * 4];
            float am[4] = {av.x, av.y, av.z, av.w};
            float bn[4] = {bv.x, bv.y, bv.z, bv.w};
#pragma unroll
            for (int i = 0; i < 4; i++)
#pragma unroll
                for (int jn = 0; jn < 4; jn++)
                    acc[i][jn] = fmaf(am[i], bn[jn], acc[i][jn]);
        }
        __syncthreads();
    }
    float4 b1 = *(const float4*)(bias1 + n0 + tx * 4);
    float4 b2 = *(const float4*)(bias2 + n0 + tx * 4);
    float bad[4] = {b1.x + b2.x, b1.y + b2.y, b1.z + b2.z, b1.w + b2.w};
#pragma unroll
    for (int i = 0; i < 4; i++) {
        float4 o;
        o.x = acc[i][0] + bad[0]; o.y = acc[i][1] + bad[1];
        o.z = acc[i][2] + bad[2]; o.w = acc[i][3] + bad[3];
        *(float4*)(C + (size_t)(m0 + ty * 4 + i) * 1024 + n0 + tx * 4) = o;
    }
}

// ============================================================================
// LSTM recurrence. 8-CTA cluster per batch element; grid = 128 CTAs x 512 thr.
// CTA rank r owns h indices [32r, 32r+32).
// R3 compute layout: thread (j = tid>>4, p = tid&15) holds W_hh rows
// g*256+base+j, cols 16p..16p+16 for all 4 gates (64 floats, f32x2-packed);
// reads 16 h floats/step from the PADDED hbuf (chunk stride 20 floats ->
// conflict-free LDS.128, 32KB/CTA/step total).
// After the 16-shfl butterfly, lanes 0/16 of warp w own (i,f,g,o) for rows
// 2w / 2w+1: activations run there (parallel across warps, no funnel, no
// __syncthreads in the loop). Lane 0 packs both h values into one b64 and
// sends it to all 8 CTAs via st.async (8 msgs/warp, 128/dest/step).
// Arrival accounting is SPLIT across two mbarrier words by source rank
// (0-3 -> barA, 4-7 -> barB, 512B each) to parallelize tx-update processing;
// consumers wait on both. Dual buffer parity (slack-2) as before.
// ============================================================================
__global__ void __cluster_dims__(8, 1, 1) __launch_bounds__(512, 1)
lstm_kernel(const float* __restrict__ Whh, const float* __restrict__ xproj,
            float* __restrict__ hout)
{
    __shared__ __align__(16) float hbuf[2][320];          // 16 chunks of 16, stride 20
    __shared__ __align__(8)  unsigned long long mbar[4];  // addr = mb0 + b*16 + g*8

    const int tid  = threadIdx.x;
    const int p    = tid & 15;
    const int j    = tid >> 4;
    const int lane = tid & 31;
    const int w    = tid >> 5;
    uint32_t rank;
    asm("mov.u32 %0, %%cluster_ctarank;" : "=r"(rank));
    const int b = blockIdx.x >> 3;
    const int base = (int)rank * 32;

    // W registers: 4 gates x 16 floats (f32x2 packed), R3 layout
    ulonglong2 W[4][4];
#pragma unroll
    for (int g = 0; g < 4; g++) {
        const ulonglong2* wp = (const ulonglong2*)(Whh + (size_t)(g * 256 + base + j) * 256 + p * 16);
#pragma unroll
        for (int i = 0; i < 4; i++) W[g][i] = wp[i];
    }

    for (int i = tid; i < 640; i += 512) (&hbuf[0][0])[i] = 0.0f;
    const uint32_t mb0 = smem_u32(&mbar[0]);
    const uint32_t hb0 = smem_u32(&hbuf[0][0]);
    if (tid == 0) {
#pragma unroll
        for (int i = 0; i < 4; i++) mbar_init_(mb0 + 8u * i, 1);
    }
    __syncthreads();
    cluster_sync_();   // peers' mbarriers + zeroed hbuf visible before any st.async

    const bool prod = (p == 0);               // lanes 0 and 16
    const int jm = 2 * w + (lane >> 4);       // producer's h row within CTA
    const float* xr = xproj + (size_t)b * 1024 * 1024 + base + jm;

    // lane 0 of each warp: remote slot of h[base+2w] in each peer's hbuf[0],
    // and each peer's group barrier (group = this CTA's rank / 4)
    uint32_t rdst[8], rmb[8];
    if (lane == 0) {
        int gidx = base + 2 * w;
        uint32_t slot = hb0 + (uint32_t)(((gidx >> 4) * 20 + (gidx & 15)) * 4);
        uint32_t gbar = mb0 + ((rank >> 2) ? 8u : 0u);
#pragma unroll
        for (int r = 0; r < 8; r++) {
            rdst[r] = mapa_(slot, (uint32_t)r);
            rmb[r]  = mapa_(gbar, (uint32_t)r);
        }
    }

    float c = 0.0f;
    float xn0 = 0.f, xn1 = 0.f, xn2 = 0.f, xn3 = 0.f;
    if (prod) { xn0 = xr[0]; xn1 = xr[256]; xn2 = xr[512]; xn3 = xr[768]; }

#pragma unroll 1
    for (int t = 0; t < 1024; t++) {
        float xc0 = xn0, xc1 = xn1, xc2 = xn2, xc3 = xn3;
        if (prod && t < 1023) {               // prefetch next step (fully hidden)
            const float* x2 = xr + (size_t)(t + 1) * 1024;
            xn0 = x2[0]; xn1 = x2[256]; xn2 = x2[512]; xn3 = x2[768];
        }
        if (t > 0) {
            uint32_t wb = mb0 + ((t & 1) ? 0u : 16u);     // barrier pair senders used
            uint32_t par = (uint32_t)(((t - 1) >> 1) & 1);
            mbar_wait_(wb, par);                          // group A
            mbar_wait_(wb + 8u, par);                     // group B
        }
        if (tid == 0 && t < 1023) {
            uint32_t eb = mb0 + ((t & 1) ? 16u : 0u);     // this step's target pair
            mbar_expect_(eb, 512);
            mbar_expect_(eb + 8u, 512);
        }

        const ulonglong2* hbp = (const ulonglong2*)(hbuf[t & 1] + p * 20);
        ulonglong2 H0 = hbp[0], H1 = hbp[1], H2 = hbp[2], H3 = hbp[3];
        u64t s0 = 0ULL, s1 = 0ULL, s2 = 0ULL, s3 = 0ULL;
#define DP(S, G) \
        S = ffma2_(W[G][0].x, H0.x, S); S = ffma2_(W[G][0].y, H0.y, S); \
        S = ffma2_(W[G][1].x, H1.x, S); S = ffma2_(W[G][1].y, H1.y, S); \
        S = ffma2_(W[G][2].x, H2.x, S); S = ffma2_(W[G][2].y, H2.y, S); \
        S = ffma2_(W[G][3].x, H3.x, S); S = ffma2_(W[G][3].y, H3.y, S);
        DP(s0, 0) DP(s1, 1) DP(s2, 2) DP(s3, 3)
#undef DP
        float f0 = pairsum_(s0), f1 = pairsum_(s1), f2 = pairsum_(s2), f3 = pairsum_(s3);
#pragma unroll
        for (int m = 1; m < 16; m <<= 1) {
            f0 += __shfl_xor_sync(0xffffffffu, f0, m);
            f1 += __shfl_xor_sync(0xffffffffu, f1, m);
            f2 += __shfl_xor_sync(0xffffffffu, f2, m);
            f3 += __shfl_xor_sync(0xffffffffu, f3, m);
        }
        // lanes 0 and 16 now hold the 4 gate sums for rows 2w / 2w+1
        float hval = 0.0f;
        if (prod) {
            float iv = sigm_(f0 + xc0);
            float fv = sigm_(f1 + xc1);
            float gg = tanh_(f2 + xc2);
            float ov = sigm_(f3 + xc3);
            c = fmaf(fv, c, iv * gg);
            hval = ov * tanh_(c);
        }
        float hhi = __shfl_sync(0xffffffffu, hval, 16);
        if (lane == 0) {
            u64t pk = (u64t)__float_as_uint(hval) | ((u64t)__float_as_uint(hhi) << 32);
            if (t < 1023) {
                uint32_t boff = (uint32_t)(((t + 1) & 1) * 1280);   // bytes
                uint32_t msel = (t & 1) ? 16u : 0u;
#pragma unroll
                for (int rr = 0; rr < 8; rr++)
                    st_async_u64_(rdst[rr] + boff, pk, rmb[rr] + msel);
            }
            *(u64t*)(hout + (size_t)(b * 1024 + t) * 256 + base + 2 * w) = pk;
        }
    }
    cluster_sync_();   // don't exit while stores targeting peers may be in flight
}

// ============================================================================
// Attention (last timestep only, algebraically reduced) + output heads.
// ============================================================================
#define ATTN_SMEM_FLOATS 17416
#define ATTN_SMEM_BYTES (ATTN_SMEM_FLOATS * 4)

__global__ void __launch_bounds__(256, 1)
attn_kernel(const float* __restrict__ h1all,
            const float* __restrict__ Wq, const float* __restrict__ bq,
            const float* __restrict__ Wk, const float* __restrict__ bk,
            const float* __restrict__ Wv, const float* __restrict__ bv,
            const float* __restrict__ Wo, const float* __restrict__ bo,
            const float* __restrict__ Wm, const float* __restrict__ bm,
            const float* __restrict__ Wvar, const float* __restrict__ bvar,
            float* __restrict__ out)
{
    extern __shared__ float sm[];
    float* tile   = sm;           // 16 x 256
    float* scores = sm + 4096;    // 8 x 1024
    float* u      = sm + 12288;   // 8 x 256
    float* hb     = sm + 14336;   // 8 x 256
    float* qv     = sm + 16384;   // 256
    float* h2last = sm + 16640;   // 256
    float* attnv  = sm + 16896;   // 256
    float* ctx    = sm + 17152;   // 256
    float* qb     = sm + 17408;   // 8

    const int b = blockIdx.x;
    const int tid = threadIdx.x;
    const int w = tid >> 5, lane = tid & 31;
    const float* hbase = h1all + (size_t)b * 1024 * 256;

    h2last[tid] = hbase[1023 * 256 + tid];
    __syncthreads();

    {
        float acc = bq[tid];
        const float* wr = Wq + (size_t)tid * 256;
#pragma unroll 8
        for (int d = 0; d < 256; d++) acc = fmaf(wr[d], h2last[d], acc);
        qv[tid] = acc;
    }
    __syncthreads();

#pragma unroll 1
    for (int i = 0; i < 8; i++) {
        int flat = tid + (i << 8);
        int hh = flat >> 8, d = flat & 255;
        float acc = 0.0f;
        const float* basep = Wk + (size_t)hh * 32 * 256 + d;
#pragma unroll
        for (int e = 0; e < 32; e++) acc = fmaf(basep[(size_t)e * 256], qv[(hh << 5) + e], acc);
        u[hh * 256 + d] = acc;
    }
    if (tid < 8) {
        float a = 0.0f;
        for (int e = 0; e < 32; e++) a = fmaf(qv[tid * 32 + e], bk[tid * 32 + e], a);
        qb[tid] = a;
    }
    __syncthreads();

    const float scale = 0.17677669529663687f;   // 1/sqrt(32)
    const float L2D   = -0.07400058144377693f;  // log2(0.95)
    const float LOG2E = 1.4426950408889634f;
    float mmax = -1e30f;

#pragma unroll 1
    for (int tt = 0; tt < 64; tt++) {
        {
            int tl = tid >> 4, d0 = (tid & 15) * 16;
            const float4* src = (const float4*)(hbase + (size_t)(tt * 16 + tl) * 256 + d0);
            float4* dst = (float4*)(tile + tl * 256 + d0);
            dst[0] = src[0]; dst[1] = src[1]; dst[2] = src[2]; dst[3] = src[3];
        }
        __syncthreads();
#pragma unroll 1
        for (int tl = 0; tl < 16; tl++) {
            int t = tt * 16 + tl;
            float part = 0.0f;
            const float* tr = tile + tl * 256 + lane * 8;
            const float* ur = u + w * 256 + lane * 8;
#pragma unroll
            for (int i = 0; i < 8; i++) part = fmaf(ur[i], tr[i], part);
#pragma unroll
            for (int m = 16; m > 0; m >>= 1) part += __shfl_xor_sync(0xffffffffu, part, m);
            float s = (part + qb[w]) * scale * fexp2_((float)(1023 - t) * L2D);
            if (lane == 0) scores[w * 1024 + t] = s;
            mmax = fmaxf(mmax, s);
        }
        __syncthreads();
    }

    float Z = 0.0f;
    for (int t = lane; t < 1024; t += 32) Z += fexp2_(LOG2E * (scores[w * 1024 + t] - mmax));
#pragma unroll
    for (int m = 16; m > 0; m >>= 1) Z += __shfl_xor_sync(0xffffffffu, Z, m);
    float invZ = 1.0f / Z;

    float hbar[8] = {0, 0, 0, 0, 0, 0, 0, 0};
#pragma unroll 1
    for (int tt = 0; tt < 64; tt++) {
        {
            int tl = tid >> 4, d0 = (tid & 15) * 16;
            const float4* src = (const float4*)(hbase + (size_t)(tt * 16 + tl) * 256 + d0);
            float4* dst = (float4*)(tile + tl * 256 + d0);
            dst[0] = src[0]; dst[1] = src[1]; dst[2] = src[2]; dst[3] = src[3];
        }
        __syncthreads();
#pragma unroll 1
        for (int tl = 0; tl < 16; tl++) {
            int t = tt * 16 + tl;
            float pr = fexp2_(LOG2E * (scores[w * 1024 + t] - mmax)) * invZ;
            const float* tr = tile + tl * 256 + lane * 8;
#pragma unroll
            for (int i = 0; i < 8; i++) hbar[i] = fmaf(pr, tr[i], hbar[i]);
        }
        __syncthreads();
    }
#pragma unroll
    for (int i = 0; i < 8; i++) hb[w * 256 + lane * 8 + i] = hbar[i];
    __syncthreads();

    {
        int hh = tid >> 5;
        float acc = bv[tid];
        const float* wr = Wv + (size_t)tid * 256;
        const float* hr = hb + hh * 256;
#pragma unroll 8
        for (int d = 0; d < 256; d++) acc = fmaf(wr[d], hr[d], acc);
        attnv[tid] = acc;
    }
    __syncthreads();
    {
        float acc = bo[tid];
        const float* wr = Wo + (size_t)tid * 256;
#pragma unroll 8
        for (int d = 0; d < 256; d++) acc = fmaf(wr[d], attnv[d], acc);
        ctx[tid] = acc;
    }
    __syncthreads();
    if (tid < 5) {
        float acc = bm[tid];
        const float* wr = Wm + (size_t)tid * 256;
#pragma unroll 8
        for (int d = 0; d < 256; d++) acc = fmaf(wr[d], ctx[d], acc);
        out[b * 5 + tid] = acc;
    } else if (tid >= 32 && tid < 37) {
        int jj = tid - 32;
        float acc = bvar[jj];
        const float* wr = Wvar + (size_t)jj * 256;
#pragma unroll 8
        for (int d = 0; d < 256; d++) acc = fmaf(wr[d], ctx[d], acc);
        out[80 + b * 5 + jj] = acc;
    }
}

// ============================================================================
extern "C" void kernel_launch(void* const* d_in, const int* in_sizes, int n_in,
                              void* d_out, int out_size)
{
    (void)in_sizes; (void)n_in; (void)out_size;
    const float* x    = (const float*)d_in[0];
    const float* Wih0 = (const float*)d_in[1];
    const float* Whh0 = (const float*)d_in[2];
    const float* bih0 = (const float*)d_in[3];
    const float* bhh0 = (const float*)d_in[4];
    const float* Wih1 = (const float*)d_in[5];
    const float* Whh1 = (const float*)d_in[6];
    const float* bih1 = (const float*)d_in[7];
    const float* bhh1 = (const float*)d_in[8];
    const float* Wq   = (const float*)d_in[9];
    const float* bq   = (const float*)d_in[10];
    const float* Wk   = (const float*)d_in[11];
    const float* bk   = (const float*)d_in[12];
    const float* Wv   = (const float*)d_in[13];
    const float* bv   = (const float*)d_in[14];
    const float* Wo   = (const float*)d_in[15];
    const float* bo   = (const float*)d_in[16];
    const float* Wm   = (const float*)d_in[17];
    const float* bm   = (const float*)d_in[18];
    const float* Wvar = (const float*)d_in[19];
    const float* bvar = (const float*)d_in[20];
    float* out = (float*)d_out;

    float *xp, *h0p, *h1p;
    cudaGetSymbolAddress((void**)&xp,  g_xproj);
    cudaGetSymbolAddress((void**)&h0p, g_h0);
    cudaGetSymbolAddress((void**)&h1p, g_h1);
    cudaFuncSetAttribute(attn_kernel, cudaFuncAttributeMaxDynamicSharedMemorySize, ATTN_SMEM_BYTES);

    gemm_xproj<<<dim3(16, 256), 256>>>(x,   Wih0, bih0, bhh0, xp, 32);
    lstm_kernel<<<128, 512>>>(Whh0, xp, h0p);
    gemm_xproj<<<dim3(16, 256), 256>>>(h0p, Wih1, bih1, bhh1, xp, 256);
    lstm_kernel<<<128, 512>>>(Whh1, xp, h1p);
    attn_kernel<<<16, 256, ATTN_SMEM_BYTES>>>(h1p, Wq, bq, Wk, bk, Wv, bv, Wo, bo,
                                              Wm, bm, Wvar, bvar, out);
}

// round 9
// speedup vs baseline: 1.2616x; 1.0109x over previous
#include <cuda_runtime.h>
#include <cstdint>
#include <cstddef>

#define DEVFN __device__ __forceinline__
typedef unsigned long long u64t;

// ---------------- static device scratch (no cudaMalloc allowed) -------------
__device__ float g_xproj[16 * 1024 * 1024]; // [bt][1024] gate pre-activations (reused for both layers)
__device__ float g_h0[16 * 1024 * 256];     // layer-0 hidden states
__device__ float g_h1[16 * 1024 * 256];     // layer-1 hidden states

// ---------------- helpers ----------------------------------------------------
DEVFN uint32_t smem_u32(const void* p) {
    uint32_t a;
    asm("{ .reg .u64 t; cvta.to.shared.u64 t, %1; cvt.u32.u64 %0, t; }" : "=r"(a) : "l"(p));
    return a;
}
DEVFN float frcp_(float x) { float r; asm("rcp.approx.f32 %0, %1;" : "=f"(r) : "f"(x)); return r; }
DEVFN float fexp2_(float x) { float r; asm("ex2.approx.f32 %0, %1;" : "=f"(r) : "f"(x)); return r; }
DEVFN float sigm_(float x) { return frcp_(1.0f + fexp2_(-1.4426950408889634f * x)); }
DEVFN float tanh_(float x) { return 1.0f - 2.0f * frcp_(1.0f + fexp2_(2.8853900817779268f * x)); }
DEVFN void cluster_sync_() {
    asm volatile("barrier.cluster.arrive.aligned;\n\tbarrier.cluster.wait.aligned;\n" ::: "memory");
}
DEVFN u64t ffma2_(u64t a, u64t b, u64t c) {
    u64t d;
    asm("fma.rn.f32x2 %0, %1, %2, %3;" : "=l"(d) : "l"(a), "l"(b), "l"(c));
    return d;
}
DEVFN float pairsum_(u64t s) {
    return __uint_as_float((uint32_t)s) + __uint_as_float((uint32_t)(s >> 32));
}
// value-folding butterfly stage: lanes with (lane&mask)==0 end up accumulating
// the 'lo' value-family, others the 'hi' family.
DEVFN float fold_(float lo, float hi, int mask, int lane) {
    float mine   = (lane & mask) ? hi : lo;
    float theirs = (lane & mask) ? lo : hi;
    return mine + __shfl_xor_sync(0xffffffffu, theirs, mask);
}
DEVFN uint32_t mapa_(uint32_t addr, uint32_t peer) {
    uint32_t r;
    asm("mapa.shared::cluster.u32 %0, %1, %2;" : "=r"(r) : "r"(addr), "r"(peer));
    return r;
}
DEVFN void mbar_init_(uint32_t a, uint32_t cnt) {
    asm volatile("mbarrier.init.shared.b64 [%0], %1;" :: "r"(a), "r"(cnt) : "memory");
}
DEVFN void mbar_expect_(uint32_t a, uint32_t bytes) {
    asm volatile("mbarrier.arrive.expect_tx.shared.b64 _, [%0], %1;" :: "r"(a), "r"(bytes) : "memory");
}
DEVFN void mbar_wait_(uint32_t a, uint32_t par) {
    asm volatile(
        "{\n\t.reg .pred P;\n\t"
        "W%=:\n\t"
        "mbarrier.try_wait.parity.acquire.cluster.shared::cta.b64 P, [%0], %1, 0x989680;\n\t"
        "@!P bra W%=;\n\t}"
        :: "r"(a), "r"(par) : "memory");
}
// remote SMEM 8-byte store with tx-byte completion on the remote CTA's mbarrier
DEVFN void st_async_u64_(uint32_t raddr, u64t v, uint32_t rmbar) {
    asm volatile(
        "st.async.shared::cluster.mbarrier::complete_tx::bytes.b64 [%0], %1, [%2];"
        :: "r"(raddr), "l"(v), "r"(rmbar) : "memory");
}

// ============================================================================
// GEMM: C[m][n] = sum_k A[m][k]*B[n][k] + bias1[n] + bias2[n]
// A: (16384, K), B: (1024, K), C: g_xproj (16384, 1024). K in {32, 256}.
// ============================================================================
__global__ void __launch_bounds__(256, 4)
gemm_xproj(const float* __restrict__ A, const float* __restrict__ B,
           const float* __restrict__ bias1, const float* __restrict__ bias2,
           float* __restrict__ C, int K)
{
    __shared__ __align__(16) float As[32][68];
    __shared__ __align__(16) float Bs[32][68];

    const int tid = threadIdx.x;
    const int tx = tid & 15, ty = tid >> 4;
    const int m0 = blockIdx.y * 64, n0 = blockIdx.x * 64;
    const int lr = tid >> 2;
    const int lcb = (tid & 3) * 4;

    float acc[4][4] = {};

    for (int kk = 0; kk < K; kk += 32) {
#pragma unroll
        for (int it = 0; it < 2; it++) {
            int k0 = lcb + it * 16;
            float4 a = *(const float4*)(A + (size_t)(m0 + lr) * K + kk + k0);
            As[k0 + 0][lr] = a.x; As[k0 + 1][lr] = a.y;
            As[k0 + 2][lr] = a.z; As[k0 + 3][lr] = a.w;
            float4 bb = *(const float4*)(B + (size_t)(n0 + lr) * K + kk + k0);
            Bs[k0 + 0][lr] = bb.x; Bs[k0 + 1][lr] = bb.y;
            Bs[k0 + 2][lr] = bb.z; Bs[k0 + 3][lr] = bb.w;
        }
        __syncthreads();
#pragma unroll
        for (int k = 0; k < 32; k++) {
            float4 av = *(const float4*)&As[k][ty * 4];
            float4 bv = *(const float4*)&Bs[k][tx * 4];
            float am[4] = {av.x, av.y, av.z, av.w};
            float bn[4] = {bv.x, bv.y, bv.z, bv.w};
#pragma unroll
            for (int i = 0; i < 4; i++)
#pragma unroll
                for (int jn = 0; jn < 4; jn++)
                    acc[i][jn] = fmaf(am[i], bn[jn], acc[i][jn]);
        }
        __syncthreads();
    }
    float4 b1 = *(const float4*)(bias1 + n0 + tx * 4);
    float4 b2 = *(const float4*)(bias2 + n0 + tx * 4);
    float bad[4] = {b1.x + b2.x, b1.y + b2.y, b1.z + b2.z, b1.w + b2.w};
#pragma unroll
    for (int i = 0; i < 4; i++) {
        float4 o;
        o.x = acc[i][0] + bad[0]; o.y = acc[i][1] + bad[1];
        o.z = acc[i][2] + bad[2]; o.w = acc[i][3] + bad[3];
        *(float4*)(C + (size_t)(m0 + ty * 4 + i) * 1024 + n0 + tx * 4) = o;
    }
}

// ============================================================================
// LSTM recurrence. 8-CTA cluster per batch element; grid = 128 CTAs x 512 thr.
// CTA rank r owns h indices [32r, 32r+32).
// Warp w owns h-rows {2w, 2w+1} for ALL 4 gates; lane l covers cols [8l,8l+8).
// Per thread: 2 LDS.128 (8 h floats, conflict-free in the stride-36 padded
// layout) + 32 ffma2 + 8 pairsums. Warp-wide: 8 sums via the 9-shfl value-
// folding butterfly: stages mask=1,2,4 fold value pairs (value index
// k = 4r + g ends at lanes {l : l&7 == k}); stages 8,16 finish the lane sum.
// Lane 0 (row 2w) and lane 4 (row 2w+1) gather their other 3 gates with 3
// shared shfl_down(1,2,3), do activations, and lane 0 packs both h values
// into one st.async.b64 per peer CTA (128 msgs -> 1024 tx bytes/dest/step).
// No __syncthreads in the loop; dual-parity mbarriers (slack-2) as proven.
// h layout: col c at float offset (c>>5)*36 + (c&31).
// ============================================================================
__global__ void __cluster_dims__(8, 1, 1) __launch_bounds__(512, 1)
lstm_kernel(const float* __restrict__ Whh, const float* __restrict__ xproj,
            float* __restrict__ hout)
{
    __shared__ __align__(16) float hbuf[2][288];          // 8 groups of 32, stride 36
    __shared__ __align__(8)  unsigned long long mbar[2];

    const int tid  = threadIdx.x;
    const int lane = tid & 31;
    const int w    = tid >> 5;
    uint32_t rank;
    asm("mov.u32 %0, %%cluster_ctarank;" : "=r"(rank));
    const int b = blockIdx.x >> 3;
    const int base = (int)rank * 32;

    // W registers: [row 0..1][gate 0..3][chunk 0..1], each chunk = 4 floats
    ulonglong2 W[2][4][2];
#pragma unroll
    for (int r = 0; r < 2; r++)
#pragma unroll
        for (int g = 0; g < 4; g++) {
            const float* row = Whh + (size_t)(g * 256 + base + 2 * w + r) * 256 + 8 * lane;
            W[r][g][0] = *(const ulonglong2*)(row);
            W[r][g][1] = *(const ulonglong2*)(row + 4);
        }

    for (int i = tid; i < 576; i += 512) (&hbuf[0][0])[i] = 0.0f;
    const uint32_t mb0 = smem_u32(&mbar[0]);              // mb1 = mb0 + 8
    const uint32_t hb0 = smem_u32(&hbuf[0][0]);
    if (tid == 0) { mbar_init_(mb0, 1); mbar_init_(mb0 + 8, 1); }
    __syncthreads();
    cluster_sync_();   // peers' mbarriers + zeroed hbuf visible before any st.async

    const bool prod = (lane & 0x1B) == 0;     // lanes 0 and 4
    const int jm = 2 * w + ((lane >> 2) & 1); // producer's h row within CTA
    const float* xr = xproj + (size_t)b * 1024 * 1024 + base + jm;

    // lane 0: remote slot of (h[base+2w], h[base+2w+1]) in each peer + barriers
    uint32_t rdst[8], rmb[8];
    if (lane == 0) {
        uint32_t slot = hb0 + (uint32_t)((int)rank * 144 + 8 * w);
#pragma unroll
        for (int r = 0; r < 8; r++) {
            rdst[r] = mapa_(slot, (uint32_t)r);
            rmb[r]  = mapa_(mb0, (uint32_t)r);   // +8 selects the other parity barrier
        }
    }

    // this thread's h read offset (floats): group l>>2, inner 8*(l&3)
    const uint32_t hoff = (uint32_t)((lane >> 2) * 36 + 8 * (lane & 3));

    float c = 0.0f;
    float xn0 = 0.f, xn1 = 0.f, xn2 = 0.f, xn3 = 0.f;
    if (prod) { xn0 = xr[0]; xn1 = xr[256]; xn2 = xr[512]; xn3 = xr[768]; }

#pragma unroll 1
    for (int t = 0; t < 1024; t++) {
        float xc0 = xn0, xc1 = xn1, xc2 = xn2, xc3 = xn3;
        if (prod && t < 1023) {               // prefetch next step (fully hidden)
            const float* x2 = xr + (size_t)(t + 1) * 1024;
            xn0 = x2[0]; xn1 = x2[256]; xn2 = x2[512]; xn3 = x2[768];
        }
        if (t > 0) mbar_wait_(mb0 + ((t & 1) ? 0u : 8u), (uint32_t)(((t - 1) >> 1) & 1));
        if (tid == 0 && t < 1023) mbar_expect_(mb0 + ((t & 1) ? 8u : 0u), 1024);

        const float* hp = hbuf[t & 1] + hoff;
        ulonglong2 H0 = *(const ulonglong2*)(hp);
        ulonglong2 H1 = *(const ulonglong2*)(hp + 4);

        // per-thread partials: v[k], k = 4*row + gate
        float v[8];
#pragma unroll
        for (int r = 0; r < 2; r++)
#pragma unroll
            for (int g = 0; g < 4; g++) {
                u64t a = ffma2_(W[r][g][0].x, H0.x, 0ULL);
                a = ffma2_(W[r][g][0].y, H0.y, a);
                a = ffma2_(W[r][g][1].x, H1.x, a);
                a = ffma2_(W[r][g][1].y, H1.y, a);
                v[r * 4 + g] = pairsum_(a);
            }

        // 9-shfl value-folding butterfly: value k -> lanes {l : l&7 == k}
        float u0 = fold_(v[0], v[1], 1, lane);   // row0: gates {i,f}
        float u1 = fold_(v[2], v[3], 1, lane);   // row0: gates {g,o}
        float u2 = fold_(v[4], v[5], 1, lane);   // row1: gates {i,f}
        float u3 = fold_(v[6], v[7], 1, lane);   // row1: gates {g,o}
        float w0 = fold_(u0, u1, 2, lane);       // row0: gate = (l&3)
        float w1 = fold_(u2, u3, 2, lane);       // row1: gate = (l&3)
        float z  = fold_(w0, w1, 4, lane);       // value = l&7
        z += __shfl_xor_sync(0xffffffffu, z, 8);
        z += __shfl_xor_sync(0xffffffffu, z, 16);

        // gather gates 1,2,3 to the activation lanes (0 and 4 share the shfls)
        float z1 = __shfl_down_sync(0xffffffffu, z, 1);
        float z2 = __shfl_down_sync(0xffffffffu, z, 2);
        float z3 = __shfl_down_sync(0xffffffffu, z, 3);

        float hval = 0.0f;
        if (prod) {
            float iv = sigm_(z  + xc0);
            float fv = sigm_(z1 + xc1);
            float gg = tanh_(z2 + xc2);
            float ov = sigm_(z3 + xc3);
            c = fmaf(fv, c, iv * gg);
            hval = ov * tanh_(c);
        }
        float hhi = __shfl_sync(0xffffffffu, hval, 4);   // lane 0 gets row 2w+1's h
        if (lane == 0) {
            u64t pk = (u64t)__float_as_uint(hval) | ((u64t)__float_as_uint(hhi) << 32);
            if (t < 1023) {
                uint32_t boff = (uint32_t)(((t + 1) & 1) * 1152);   // hbuf stride bytes
                uint32_t msel = (t & 1) ? 8u : 0u;
#pragma unroll
                for (int rr = 0; rr < 8; rr++)
                    st_async_u64_(rdst[rr] + boff, pk, rmb[rr] + msel);
            }
            *(u64t*)(hout + (size_t)(b * 1024 + t) * 256 + base + 2 * w) = pk;
        }
    }
    cluster_sync_();   // don't exit while stores targeting peers may be in flight
}

// ============================================================================
// Attention (last timestep only, algebraically reduced) + output heads.
// ============================================================================
#define ATTN_SMEM_FLOATS 17416
#define ATTN_SMEM_BYTES (ATTN_SMEM_FLOATS * 4)

__global__ void __launch_bounds__(256, 1)
attn_kernel(const float* __restrict__ h1all,
            const float* __restrict__ Wq, const float* __restrict__ bq,
            const float* __restrict__ Wk, const float* __restrict__ bk,
            const float* __restrict__ Wv, const float* __restrict__ bv,
            const float* __restrict__ Wo, const float* __restrict__ bo,
            const float* __restrict__ Wm, const float* __restrict__ bm,
            const float* __restrict__ Wvar, const float* __restrict__ bvar,
            float* __restrict__ out)
{
    extern __shared__ float sm[];
    float* tile   = sm;           // 16 x 256
    float* scores = sm + 4096;    // 8 x 1024
    float* u      = sm + 12288;   // 8 x 256
    float* hb     = sm + 14336;   // 8 x 256
    float* qv     = sm + 16384;   // 256
    float* h2last = sm + 16640;   // 256
    float* attnv  = sm + 16896;   // 256
    float* ctx    = sm + 17152;   // 256
    float* qb     = sm + 17408;   // 8

    const int b = blockIdx.x;
    const int tid = threadIdx.x;
    const int w = tid >> 5, lane = tid & 31;
    const float* hbase = h1all + (size_t)b * 1024 * 256;

    h2last[tid] = hbase[1023 * 256 + tid];
    __syncthreads();

    {
        float acc = bq[tid];
        const float* wr = Wq + (size_t)tid * 256;
#pragma unroll 8
        for (int d = 0; d < 256; d++) acc = fmaf(wr[d], h2last[d], acc);
        qv[tid] = acc;
    }
    __syncthreads();

#pragma unroll 1
    for (int i = 0; i < 8; i++) {
        int flat = tid + (i << 8);
        int hh = flat >> 8, d = flat & 255;
        float acc = 0.0f;
        const float* basep = Wk + (size_t)hh * 32 * 256 + d;
#pragma unroll
        for (int e = 0; e < 32; e++) acc = fmaf(basep[(size_t)e * 256], qv[(hh << 5) + e], acc);
        u[hh * 256 + d] = acc;
    }
    if (tid < 8) {
        float a = 0.0f;
        for (int e = 0; e < 32; e++) a = fmaf(qv[tid * 32 + e], bk[tid * 32 + e], a);
        qb[tid] = a;
    }
    __syncthreads();

    const float scale = 0.17677669529663687f;   // 1/sqrt(32)
    const float L2D   = -0.07400058144377693f;  // log2(0.95)
    const float LOG2E = 1.4426950408889634f;
    float mmax = -1e30f;

#pragma unroll 1
    for (int tt = 0; tt < 64; tt++) {
        {
            int tl = tid >> 4, d0 = (tid & 15) * 16;
            const float4* src = (const float4*)(hbase + (size_t)(tt * 16 + tl) * 256 + d0);
            float4* dst = (float4*)(tile + tl * 256 + d0);
            dst[0] = src[0]; dst[1] = src[1]; dst[2] = src[2]; dst[3] = src[3];
        }
        __syncthreads();
#pragma unroll 1
        for (int tl = 0; tl < 16; tl++) {
            int t = tt * 16 + tl;
            float part = 0.0f;
            const float* tr = tile + tl * 256 + lane * 8;
            const float* ur = u + w * 256 + lane * 8;
#pragma unroll
            for (int i = 0; i < 8; i++) part = fmaf(ur[i], tr[i], part);
#pragma unroll
            for (int m = 16; m > 0; m >>= 1) part += __shfl_xor_sync(0xffffffffu, part, m);
            float s = (part + qb[w]) * scale * fexp2_((float)(1023 - t) * L2D);
            if (lane == 0) scores[w * 1024 + t] = s;
            mmax = fmaxf(mmax, s);
        }
        __syncthreads();
    }

    float Z = 0.0f;
    for (int t = lane; t < 1024; t += 32) Z += fexp2_(LOG2E * (scores[w * 1024 + t] - mmax));
#pragma unroll
    for (int m = 16; m > 0; m >>= 1) Z += __shfl_xor_sync(0xffffffffu, Z, m);
    float invZ = 1.0f / Z;

    float hbar[8] = {0, 0, 0, 0, 0, 0, 0, 0};
#pragma unroll 1
    for (int tt = 0; tt < 64; tt++) {
        {
            int tl = tid >> 4, d0 = (tid & 15) * 16;
            const float4* src = (const float4*)(hbase + (size_t)(tt * 16 + tl) * 256 + d0);
            float4* dst = (float4*)(tile + tl * 256 + d0);
            dst[0] = src[0]; dst[1] = src[1]; dst[2] = src[2]; dst[3] = src[3];
        }
        __syncthreads();
#pragma unroll 1
        for (int tl = 0; tl < 16; tl++) {
            int t = tt * 16 + tl;
            float pr = fexp2_(LOG2E * (scores[w * 1024 + t] - mmax)) * invZ;
            const float* tr = tile + tl * 256 + lane * 8;
#pragma unroll
            for (int i = 0; i < 8; i++) hbar[i] = fmaf(pr, tr[i], hbar[i]);
        }
        __syncthreads();
    }
#pragma unroll
    for (int i = 0; i < 8; i++) hb[w * 256 + lane * 8 + i] = hbar[i];
    __syncthreads();

    {
        int hh = tid >> 5;
        float acc = bv[tid];
        const float* wr = Wv + (size_t)tid * 256;
        const float* hr = hb + hh * 256;
#pragma unroll 8
        for (int d = 0; d < 256; d++) acc = fmaf(wr[d], hr[d], acc);
        attnv[tid] = acc;
    }
    __syncthreads();
    {
        float acc = bo[tid];
        const float* wr = Wo + (size_t)tid * 256;
#pragma unroll 8
        for (int d = 0; d < 256; d++) acc = fmaf(wr[d], attnv[d], acc);
        ctx[tid] = acc;
    }
    __syncthreads();
    if (tid < 5) {
        float acc = bm[tid];
        const float* wr = Wm + (size_t)tid * 256;
#pragma unroll 8
        for (int d = 0; d < 256; d++) acc = fmaf(wr[d], ctx[d], acc);
        out[b * 5 + tid] = acc;
    } else if (tid >= 32 && tid < 37) {
        int jj = tid - 32;
        float acc = bvar[jj];
        const float* wr = Wvar + (size_t)jj * 256;
#pragma unroll 8
        for (int d = 0; d < 256; d++) acc = fmaf(wr[d], ctx[d], acc);
        out[80 + b * 5 + jj] = acc;
    }
}

// ============================================================================
extern "C" void kernel_launch(void* const* d_in, const int* in_sizes, int n_in,
                              void* d_out, int out_size)
{
    (void)in_sizes; (void)n_in; (void)out_size;
    const float* x    = (const float*)d_in[0];
    const float* Wih0 = (const float*)d_in[1];
    const float* Whh0 = (const float*)d_in[2];
    const float* bih0 = (const float*)d_in[3];
    const float* bhh0 = (const float*)d_in[4];
    const float* Wih1 = (const float*)d_in[5];
    const float* Whh1 = (const float*)d_in[6];
    const float* bih1 = (const float*)d_in[7];
    const float* bhh1 = (const float*)d_in[8];
    const float* Wq   = (const float*)d_in[9];
    const float* bq   = (const float*)d_in[10];
    const float* Wk   = (const float*)d_in[11];
    const float* bk   = (const float*)d_in[12];
    const float* Wv   = (const float*)d_in[13];
    const float* bv   = (const float*)d_in[14];
    const float* Wo   = (const float*)d_in[15];
    const float* bo   = (const float*)d_in[16];
    const float* Wm   = (const float*)d_in[17];
    const float* bm   = (const float*)d_in[18];
    const float* Wvar = (const float*)d_in[19];
    const float* bvar = (const float*)d_in[20];
    float* out = (float*)d_out;

    float *xp, *h0p, *h1p;
    cudaGetSymbolAddress((void**)&xp,  g_xproj);
    cudaGetSymbolAddress((void**)&h0p, g_h0);
    cudaGetSymbolAddress((void**)&h1p, g_h1);
    cudaFuncSetAttribute(attn_kernel, cudaFuncAttributeMaxDynamicSharedMemorySize, ATTN_SMEM_BYTES);

    gemm_xproj<<<dim3(16, 256), 256>>>(x,   Wih0, bih0, bhh0, xp, 32);
    lstm_kernel<<<128, 512>>>(Whh0, xp, h0p);
    gemm_xproj<<<dim3(16, 256), 256>>>(h0p, Wih1, bih1, bhh1, xp, 256);
    lstm_kernel<<<128, 512>>>(Whh1, xp, h1p);
    attn_kernel<<<16, 256, ATTN_SMEM_BYTES>>>(h1p, Wq, bq, Wk, bk, Wv, bv, Wo, bo,
                                              Wm, bm, Wvar, bvar, out);
}

// round 10
// speedup vs baseline: 1.2861x; 1.0194x over previous
#include <cuda_runtime.h>
#include <cstdint>
#include <cstddef>

#define DEVFN __device__ __forceinline__
typedef unsigned long long u64t;

// ---------------- static device scratch (no cudaMalloc allowed) -------------
__device__ float g_xproj[16 * 1024 * 1024]; // [bt][1024] gate pre-activations (reused for both layers)
__device__ float g_h0[16 * 1024 * 256];     // layer-0 hidden states
__device__ float g_h1[16 * 1024 * 256];     // layer-1 hidden states

// ---------------- helpers ----------------------------------------------------
DEVFN uint32_t smem_u32(const void* p) {
    uint32_t a;
    asm("{ .reg .u64 t; cvta.to.shared.u64 t, %1; cvt.u32.u64 %0, t; }" : "=r"(a) : "l"(p));
    return a;
}
DEVFN float frcp_(float x) { float r; asm("rcp.approx.f32 %0, %1;" : "=f"(r) : "f"(x)); return r; }
DEVFN float fexp2_(float x) { float r; asm("ex2.approx.f32 %0, %1;" : "=f"(r) : "f"(x)); return r; }
DEVFN float sigm_(float x) { return frcp_(1.0f + fexp2_(-1.4426950408889634f * x)); }
DEVFN float tanh_(float x) { return 1.0f - 2.0f * frcp_(1.0f + fexp2_(2.8853900817779268f * x)); }
DEVFN void cluster_sync_() {
    asm volatile("barrier.cluster.arrive.aligned;\n\tbarrier.cluster.wait.aligned;\n" ::: "memory");
}
DEVFN u64t ffma2_(u64t a, u64t b, u64t c) {
    u64t d;
    asm("fma.rn.f32x2 %0, %1, %2, %3;" : "=l"(d) : "l"(a), "l"(b), "l"(c));
    return d;
}
DEVFN float pairsum_(u64t s) {
    return __uint_as_float((uint32_t)s) + __uint_as_float((uint32_t)(s >> 32));
}
// value-folding butterfly stage: lanes with (lane&mask)==0 end up accumulating
// the 'lo' value-family, others the 'hi' family.
DEVFN float fold_(float lo, float hi, int mask, int lane) {
    float mine   = (lane & mask) ? hi : lo;
    float theirs = (lane & mask) ? lo : hi;
    return mine + __shfl_xor_sync(0xffffffffu, theirs, mask);
}
DEVFN uint32_t mapa_(uint32_t addr, uint32_t peer) {
    uint32_t r;
    asm("mapa.shared::cluster.u32 %0, %1, %2;" : "=r"(r) : "r"(addr), "r"(peer));
    return r;
}
DEVFN void mbar_init_(uint32_t a, uint32_t cnt) {
    asm volatile("mbarrier.init.shared.b64 [%0], %1;" :: "r"(a), "r"(cnt) : "memory");
}
DEVFN void mbar_expect_(uint32_t a, uint32_t bytes) {
    asm volatile("mbarrier.arrive.expect_tx.shared.b64 _, [%0], %1;" :: "r"(a), "r"(bytes) : "memory");
}
// CTA-scope acquire wait (canonical async-proxy consumer pattern — matches
// MBARRIER_WAIT_PARITY in ptx_helpers; the complete_tx machinery already
// guarantees fabric-delivered SMEM data is CTA-visible at phase flip).
// The previous .acquire.cluster variant implies a >=cluster-scope fence
// (CCTL.IVALL class) in EVERY warp EVERY step — the suspected invariant cost.
DEVFN void mbar_wait_(uint32_t a, uint32_t par) {
    asm volatile(
        "{\n\t.reg .pred P;\n\t"
        "W%=:\n\t"
        "mbarrier.try_wait.parity.acquire.cta.shared::cta.b64 P, [%0], %1, 0x989680;\n\t"
        "@!P bra W%=;\n\t}"
        :: "r"(a), "r"(par) : "memory");
}
// remote SMEM 8-byte store with tx-byte completion on the remote CTA's mbarrier
DEVFN void st_async_u64_(uint32_t raddr, u64t v, uint32_t rmbar) {
    asm volatile(
        "st.async.shared::cluster.mbarrier::complete_tx::bytes.b64 [%0], %1, [%2];"
        :: "r"(raddr), "l"(v), "r"(rmbar) : "memory");
}

// ============================================================================
// GEMM: C[m][n] = sum_k A[m][k]*B[n][k] + bias1[n] + bias2[n]
// A: (16384, K), B: (1024, K), C: g_xproj (16384, 1024). K in {32, 256}.
// ============================================================================
__global__ void __launch_bounds__(256, 4)
gemm_xproj(const float* __restrict__ A, const float* __restrict__ B,
           const float* __restrict__ bias1, const float* __restrict__ bias2,
           float* __restrict__ C, int K)
{
    __shared__ __align__(16) float As[32][68];
    __shared__ __align__(16) float Bs[32][68];

    const int tid = threadIdx.x;
    const int tx = tid & 15, ty = tid >> 4;
    const int m0 = blockIdx.y * 64, n0 = blockIdx.x * 64;
    const int lr = tid >> 2;
    const int lcb = (tid & 3) * 4;

    float acc[4][4] = {};

    for (int kk = 0; kk < K; kk += 32) {
#pragma unroll
        for (int it = 0; it < 2; it++) {
            int k0 = lcb + it * 16;
            float4 a = *(const float4*)(A + (size_t)(m0 + lr) * K + kk + k0);
            As[k0 + 0][lr] = a.x; As[k0 + 1][lr] = a.y;
            As[k0 + 2][lr] = a.z; As[k0 + 3][lr] = a.w;
            float4 bb = *(const float4*)(B + (size_t)(n0 + lr) * K + kk + k0);
            Bs[k0 + 0][lr] = bb.x; Bs[k0 + 1][lr] = bb.y;
            Bs[k0 + 2][lr] = bb.z; Bs[k0 + 3][lr] = bb.w;
        }
        __syncthreads();
#pragma unroll
        for (int k = 0; k < 32; k++) {
            float4 av = *(const float4*)&As[k][ty * 4];
            float4 bv = *(const float4*)&Bs[k][tx * 4];
            float am[4] = {av.x, av.y, av.z, av.w};
            float bn[4] = {bv.x, bv.y, bv.z, bv.w};
#pragma unroll
            for (int i = 0; i < 4; i++)
#pragma unroll
                for (int jn = 0; jn < 4; jn++)
                    acc[i][jn] = fmaf(am[i], bn[jn], acc[i][jn]);
        }
        __syncthreads();
    }
    float4 b1 = *(const float4*)(bias1 + n0 + tx * 4);
    float4 b2 = *(const float4*)(bias2 + n0 + tx * 4);
    float bad[4] = {b1.x + b2.x, b1.y + b2.y, b1.z + b2.z, b1.w + b2.w};
#pragma unroll
    for (int i = 0; i < 4; i++) {
        float4 o;
        o.x = acc[i][0] + bad[0]; o.y = acc[i][1] + bad[1];
        o.z = acc[i][2] + bad[2]; o.w = acc[i][3] + bad[3];
        *(float4*)(C + (size_t)(m0 + ty * 4 + i) * 1024 + n0 + tx * 4) = o;
    }
}

// ============================================================================
// LSTM recurrence. 8-CTA cluster per batch element; grid = 128 CTAs x 512 thr.
// CTA rank r owns h indices [32r, 32r+32).
// Warp w owns h-rows {2w, 2w+1} for ALL 4 gates; lane l covers cols [8l,8l+8).
// Per thread: 2 LDS.128 (8 h floats, conflict-free in the stride-36 padded
// layout) + 32 ffma2 + 8 pairsums. Warp-wide: 8 sums via the 9-shfl value-
// folding butterfly; lanes 0/4 do activations; lane 0 packs both h values
// into one st.async.b64 per peer CTA. No __syncthreads in the loop;
// dual-parity mbarriers (slack-2); waits use CTA-scope acquire (the one
// change vs R8 — cluster-scope acquire implied a heavyweight per-warp fence
// every step, the suspected flat ~1.7ms/layer floor).
// h layout: col c at float offset (c>>5)*36 + (c&31).
// ============================================================================
__global__ void __cluster_dims__(8, 1, 1) __launch_bounds__(512, 1)
lstm_kernel(const float* __restrict__ Whh, const float* __restrict__ xproj,
            float* __restrict__ hout)
{
    __shared__ __align__(16) float hbuf[2][288];          // 8 groups of 32, stride 36
    __shared__ __align__(8)  unsigned long long mbar[2];

    const int tid  = threadIdx.x;
    const int lane = tid & 31;
    const int w    = tid >> 5;
    uint32_t rank;
    asm("mov.u32 %0, %%cluster_ctarank;" : "=r"(rank));
    const int b = blockIdx.x >> 3;
    const int base = (int)rank * 32;

    // W registers: [row 0..1][gate 0..3][chunk 0..1], each chunk = 4 floats
    ulonglong2 W[2][4][2];
#pragma unroll
    for (int r = 0; r < 2; r++)
#pragma unroll
        for (int g = 0; g < 4; g++) {
            const float* row = Whh + (size_t)(g * 256 + base + 2 * w + r) * 256 + 8 * lane;
            W[r][g][0] = *(const ulonglong2*)(row);
            W[r][g][1] = *(const ulonglong2*)(row + 4);
        }

    for (int i = tid; i < 576; i += 512) (&hbuf[0][0])[i] = 0.0f;
    const uint32_t mb0 = smem_u32(&mbar[0]);              // mb1 = mb0 + 8
    const uint32_t hb0 = smem_u32(&hbuf[0][0]);
    if (tid == 0) { mbar_init_(mb0, 1); mbar_init_(mb0 + 8, 1); }
    __syncthreads();
    cluster_sync_();   // peers' mbarriers + zeroed hbuf visible before any st.async

    const bool prod = (lane & 0x1B) == 0;     // lanes 0 and 4
    const int jm = 2 * w + ((lane >> 2) & 1); // producer's h row within CTA
    const float* xr = xproj + (size_t)b * 1024 * 1024 + base + jm;

    // lane 0: remote slot of (h[base+2w], h[base+2w+1]) in each peer + barriers
    uint32_t rdst[8], rmb[8];
    if (lane == 0) {
        uint32_t slot = hb0 + (uint32_t)((int)rank * 144 + 8 * w);
#pragma unroll
        for (int r = 0; r < 8; r++) {
            rdst[r] = mapa_(slot, (uint32_t)r);
            rmb[r]  = mapa_(mb0, (uint32_t)r);   // +8 selects the other parity barrier
        }
    }

    // this thread's h read offset (floats): group l>>2, inner 8*(l&3)
    const uint32_t hoff = (uint32_t)((lane >> 2) * 36 + 8 * (lane & 3));

    float c = 0.0f;
    float xn0 = 0.f, xn1 = 0.f, xn2 = 0.f, xn3 = 0.f;
    if (prod) { xn0 = xr[0]; xn1 = xr[256]; xn2 = xr[512]; xn3 = xr[768]; }

#pragma unroll 1
    for (int t = 0; t < 1024; t++) {
        float xc0 = xn0, xc1 = xn1, xc2 = xn2, xc3 = xn3;
        if (prod && t < 1023) {               // prefetch next step (fully hidden)
            const float* x2 = xr + (size_t)(t + 1) * 1024;
            xn0 = x2[0]; xn1 = x2[256]; xn2 = x2[512]; xn3 = x2[768];
        }
        if (t > 0) mbar_wait_(mb0 + ((t & 1) ? 0u : 8u), (uint32_t)(((t - 1) >> 1) & 1));
        if (tid == 0 && t < 1023) mbar_expect_(mb0 + ((t & 1) ? 8u : 0u), 1024);

        const float* hp = hbuf[t & 1] + hoff;
        ulonglong2 H0 = *(const ulonglong2*)(hp);
        ulonglong2 H1 = *(const ulonglong2*)(hp + 4);

        // per-thread partials: v[k], k = 4*row + gate
        float v[8];
#pragma unroll
        for (int r = 0; r < 2; r++)
#pragma unroll
            for (int g = 0; g < 4; g++) {
                u64t a = ffma2_(W[r][g][0].x, H0.x, 0ULL);
                a = ffma2_(W[r][g][0].y, H0.y, a);
                a = ffma2_(W[r][g][1].x, H1.x, a);
                a = ffma2_(W[r][g][1].y, H1.y, a);
                v[r * 4 + g] = pairsum_(a);
            }

        // 9-shfl value-folding butterfly: value k -> lanes {l : l&7 == k}
        float u0 = fold_(v[0], v[1], 1, lane);   // row0: gates {i,f}
        float u1 = fold_(v[2], v[3], 1, lane);   // row0: gates {g,o}
        float u2 = fold_(v[4], v[5], 1, lane);   // row1: gates {i,f}
        float u3 = fold_(v[6], v[7], 1, lane);   // row1: gates {g,o}
        float w0 = fold_(u0, u1, 2, lane);       // row0: gate = (l&3)
        float w1 = fold_(u2, u3, 2, lane);       // row1: gate = (l&3)
        float z  = fold_(w0, w1, 4, lane);       // value = l&7
        z += __shfl_xor_sync(0xffffffffu, z, 8);
        z += __shfl_xor_sync(0xffffffffu, z, 16);

        // gather gates 1,2,3 to the activation lanes (0 and 4 share the shfls)
        float z1 = __shfl_down_sync(0xffffffffu, z, 1);
        float z2 = __shfl_down_sync(0xffffffffu, z, 2);
        float z3 = __shfl_down_sync(0xffffffffu, z, 3);

        float hval = 0.0f;
        if (prod) {
            float iv = sigm_(z  + xc0);
            float fv = sigm_(z1 + xc1);
            float gg = tanh_(z2 + xc2);
            float ov = sigm_(z3 + xc3);
            c = fmaf(fv, c, iv * gg);
            hval = ov * tanh_(c);
        }
        float hhi = __shfl_sync(0xffffffffu, hval, 4);   // lane 0 gets row 2w+1's h
        if (lane == 0) {
            u64t pk = (u64t)__float_as_uint(hval) | ((u64t)__float_as_uint(hhi) << 32);
            if (t < 1023) {
                uint32_t boff = (uint32_t)(((t + 1) & 1) * 1152);   // hbuf stride bytes
                uint32_t msel = (t & 1) ? 8u : 0u;
#pragma unroll
                for (int rr = 0; rr < 8; rr++)
                    st_async_u64_(rdst[rr] + boff, pk, rmb[rr] + msel);
            }
            *(u64t*)(hout + (size_t)(b * 1024 + t) * 256 + base + 2 * w) = pk;
        }
    }
    cluster_sync_();   // don't exit while stores targeting peers may be in flight
}

// ============================================================================
// Attention (last timestep only, algebraically reduced) + output heads.
// ============================================================================
#define ATTN_SMEM_FLOATS 17416
#define ATTN_SMEM_BYTES (ATTN_SMEM_FLOATS * 4)

__global__ void __launch_bounds__(256, 1)
attn_kernel(const float* __restrict__ h1all,
            const float* __restrict__ Wq, const float* __restrict__ bq,
            const float* __restrict__ Wk, const float* __restrict__ bk,
            const float* __restrict__ Wv, const float* __restrict__ bv,
            const float* __restrict__ Wo, const float* __restrict__ bo,
            const float* __restrict__ Wm, const float* __restrict__ bm,
            const float* __restrict__ Wvar, const float* __restrict__ bvar,
            float* __restrict__ out)
{
    extern __shared__ float sm[];
    float* tile   = sm;           // 16 x 256
    float* scores = sm + 4096;    // 8 x 1024
    float* u      = sm + 12288;   // 8 x 256
    float* hb     = sm + 14336;   // 8 x 256
    float* qv     = sm + 16384;   // 256
    float* h2last = sm + 16640;   // 256
    float* attnv  = sm + 16896;   // 256
    float* ctx    = sm + 17152;   // 256
    float* qb     = sm + 17408;   // 8

    const int b = blockIdx.x;
    const int tid = threadIdx.x;
    const int w = tid >> 5, lane = tid & 31;
    const float* hbase = h1all + (size_t)b * 1024 * 256;

    h2last[tid] = hbase[1023 * 256 + tid];
    __syncthreads();

    {
        float acc = bq[tid];
        const float* wr = Wq + (size_t)tid * 256;
#pragma unroll 8
        for (int d = 0; d < 256; d++) acc = fmaf(wr[d], h2last[d], acc);
        qv[tid] = acc;
    }
    __syncthreads();

#pragma unroll 1
    for (int i = 0; i < 8; i++) {
        int flat = tid + (i << 8);
        int hh = flat >> 8, d = flat & 255;
        float acc = 0.0f;
        const float* basep = Wk + (size_t)hh * 32 * 256 + d;
#pragma unroll
        for (int e = 0; e < 32; e++) acc = fmaf(basep[(size_t)e * 256], qv[(hh << 5) + e], acc);
        u[hh * 256 + d] = acc;
    }
    if (tid < 8) {
        float a = 0.0f;
        for (int e = 0; e < 32; e++) a = fmaf(qv[tid * 32 + e], bk[tid * 32 + e], a);
        qb[tid] = a;
    }
    __syncthreads();

    const float scale = 0.17677669529663687f;   // 1/sqrt(32)
    const float L2D   = -0.07400058144377693f;  // log2(0.95)
    const float LOG2E = 1.4426950408889634f;
    float mmax = -1e30f;

#pragma unroll 1
    for (int tt = 0; tt < 64; tt++) {
        {
            int tl = tid >> 4, d0 = (tid & 15) * 16;
            const float4* src = (const float4*)(hbase + (size_t)(tt * 16 + tl) * 256 + d0);
            float4* dst = (float4*)(tile + tl * 256 + d0);
            dst[0] = src[0]; dst[1] = src[1]; dst[2] = src[2]; dst[3] = src[3];
        }
        __syncthreads();
#pragma unroll 1
        for (int tl = 0; tl < 16; tl++) {
            int t = tt * 16 + tl;
            float part = 0.0f;
            const float* tr = tile + tl * 256 + lane * 8;
            const float* ur = u + w * 256 + lane * 8;
#pragma unroll
            for (int i = 0; i < 8; i++) part = fmaf(ur[i], tr[i], part);
#pragma unroll
            for (int m = 16; m > 0; m >>= 1) part += __shfl_xor_sync(0xffffffffu, part, m);
            float s = (part + qb[w]) * scale * fexp2_((float)(1023 - t) * L2D);
            if (lane == 0) scores[w * 1024 + t] = s;
            mmax = fmaxf(mmax, s);
        }
        __syncthreads();
    }

    float Z = 0.0f;
    for (int t = lane; t < 1024; t += 32) Z += fexp2_(LOG2E * (scores[w * 1024 + t] - mmax));
#pragma unroll
    for (int m = 16; m > 0; m >>= 1) Z += __shfl_xor_sync(0xffffffffu, Z, m);
    float invZ = 1.0f / Z;

    float hbar[8] = {0, 0, 0, 0, 0, 0, 0, 0};
#pragma unroll 1
    for (int tt = 0; tt < 64; tt++) {
        {
            int tl = tid >> 4, d0 = (tid & 15) * 16;
            const float4* src = (const float4*)(hbase + (size_t)(tt * 16 + tl) * 256 + d0);
            float4* dst = (float4*)(tile + tl * 256 + d0);
            dst[0] = src[0]; dst[1] = src[1]; dst[2] = src[2]; dst[3] = src[3];
        }
        __syncthreads();
#pragma unroll 1
        for (int tl = 0; tl < 16; tl++) {
            int t = tt * 16 + tl;
            float pr = fexp2_(LOG2E * (scores[w * 1024 + t] - mmax)) * invZ;
            const float* tr = tile + tl * 256 + lane * 8;
#pragma unroll
            for (int i = 0; i < 8; i++) hbar[i] = fmaf(pr, tr[i], hbar[i]);
        }
        __syncthreads();
    }
#pragma unroll
    for (int i = 0; i < 8; i++) hb[w * 256 + lane * 8 + i] = hbar[i];
    __syncthreads();

    {
        int hh = tid >> 5;
        float acc = bv[tid];
        const float* wr = Wv + (size_t)tid * 256;
        const float* hr = hb + hh * 256;
#pragma unroll 8
        for (int d = 0; d < 256; d++) acc = fmaf(wr[d], hr[d], acc);
        attnv[tid] = acc;
    }
    __syncthreads();
    {
        float acc = bo[tid];
        const float* wr = Wo + (size_t)tid * 256;
#pragma unroll 8
        for (int d = 0; d < 256; d++) acc = fmaf(wr[d], attnv[d], acc);
        ctx[tid] = acc;
    }
    __syncthreads();
    if (tid < 5) {
        float acc = bm[tid];
        const float* wr = Wm + (size_t)tid * 256;
#pragma unroll 8
        for (int d = 0; d < 256; d++) acc = fmaf(wr[d], ctx[d], acc);
        out[b * 5 + tid] = acc;
    } else if (tid >= 32 && tid < 37) {
        int jj = tid - 32;
        float acc = bvar[jj];
        const float* wr = Wvar + (size_t)jj * 256;
#pragma unroll 8
        for (int d = 0; d < 256; d++) acc = fmaf(wr[d], ctx[d], acc);
        out[80 + b * 5 + jj] = acc;
    }
}

// ============================================================================
extern "C" void kernel_launch(void* const* d_in, const int* in_sizes, int n_in,
                              void* d_out, int out_size)
{
    (void)in_sizes; (void)n_in; (void)out_size;
    const float* x    = (const float*)d_in[0];
    const float* Wih0 = (const float*)d_in[1];
    const float* Whh0 = (const float*)d_in[2];
    const float* bih0 = (const float*)d_in[3];
    const float* bhh0 = (const float*)d_in[4];
    const float* Wih1 = (const float*)d_in[5];
    const float* Whh1 = (const float*)d_in[6];
    const float* bih1 = (const float*)d_in[7];
    const float* bhh1 = (const float*)d_in[8];
    const float* Wq   = (const float*)d_in[9];
    const float* bq   = (const float*)d_in[10];
    const float* Wk   = (const float*)d_in[11];
    const float* bk   = (const float*)d_in[12];
    const float* Wv   = (const float*)d_in[13];
    const float* bv   = (const float*)d_in[14];
    const float* Wo   = (const float*)d_in[15];
    const float* bo   = (const float*)d_in[16];
    const float* Wm   = (const float*)d_in[17];
    const float* bm   = (const float*)d_in[18];
    const float* Wvar = (const float*)d_in[19];
    const float* bvar = (const float*)d_in[20];
    float* out = (float*)d_out;

    float *xp, *h0p, *h1p;
    cudaGetSymbolAddress((void**)&xp,  g_xproj);
    cudaGetSymbolAddress((void**)&h0p, g_h0);
    cudaGetSymbolAddress((void**)&h1p, g_h1);
    cudaFuncSetAttribute(attn_kernel, cudaFuncAttributeMaxDynamicSharedMemorySize, ATTN_SMEM_BYTES);

    gemm_xproj<<<dim3(16, 256), 256>>>(x,   Wih0, bih0, bhh0, xp, 32);
    lstm_kernel<<<128, 512>>>(Whh0, xp, h0p);
    gemm_xproj<<<dim3(16, 256), 256>>>(h0p, Wih1, bih1, bhh1, xp, 256);
    lstm_kernel<<<128, 512>>>(Whh1, xp, h1p);
    attn_kernel<<<16, 256, ATTN_SMEM_BYTES>>>(h1p, Wq, bq, Wk, bk, Wv, bv, Wo, bo,
                                              Wm, bm, Wvar, bvar, out);
}